// round 13
// baseline (speedup 1.0000x reference)
#include <cuda_runtime.h>
#include <cuda_fp16.h>
#include <cstdint>
#include <cstddef>

// ---------------------------------------------------------------------------
// Problem constants
// ---------------------------------------------------------------------------
#define N_TOK   8192
#define DIN     4096
#define DOUT    4096
#define S_RANK  256
#define S_CAT   512

#define BM      128
#define BN      128
#define BK      64          // 64 fp16 = 128B row -> SW128 swizzle
#define STAGES  3
#define THREADS 256

#define TILE_BYTES (128 * 128)                       // 16KB per fp16 tile stage
#define G_SMEM     (STAGES * 2 * TILE_BYTES)         // 98304 -> 2 CTAs/SM

// ---------------------------------------------------------------------------
// Scratch (device globals; no runtime allocation)
// ---------------------------------------------------------------------------
__device__ __half g_xh[(size_t)N_TOK * DIN];     // fp16(x)            64 MB
__device__ __half g_B1[(size_t)S_CAT * DIN];     // sign(V)*v2*v1*u2    4 MB
__device__ __half g_B2[(size_t)DOUT * S_CAT];    // sign(U)*u1          4 MB
__device__ __half g_H [(size_t)N_TOK * S_CAT];   // H fp16              8 MB

// ---------------------------------------------------------------------------
// Helpers
// ---------------------------------------------------------------------------
__device__ __forceinline__ uint32_t smem_u32(const void* p) {
    uint32_t a;
    asm("{ .reg .u64 t; cvta.to.shared.u64 t, %1; cvt.u32.u64 %0, t; }" : "=r"(a) : "l"(p));
    return a;
}

#define SWZ(o) ((o) ^ (((o) >> 3) & 0x70))

#define CP_ASYNC16(s, g) \
    asm volatile("cp.async.cg.shared.global [%0], [%1], 16;" :: "r"(s), "l"(g))
#define CP_COMMIT() asm volatile("cp.async.commit_group;")
#define CP_WAIT(n)  asm volatile("cp.async.wait_group %0;" :: "n"(n) : "memory")

#define LDMATRIX_X4(r0, r1, r2, r3, addr)                                     \
    asm volatile("ldmatrix.sync.aligned.m8n8.x4.shared.b16 {%0,%1,%2,%3}, [%4];" \
        : "=r"(r0), "=r"(r1), "=r"(r2), "=r"(r3) : "r"(addr))

#define MMA_16816(d, a, b0, b1)                                               \
    asm volatile("mma.sync.aligned.m16n8k16.row.col.f32.f16.f16.f32 "         \
        "{%0,%1,%2,%3}, {%4,%5,%6,%7}, {%8,%9}, {%0,%1,%2,%3};"               \
        : "+f"((d)[0]), "+f"((d)[1]), "+f"((d)[2]), "+f"((d)[3])              \
        : "r"((a)[0]), "r"((a)[1]), "r"((a)[2]), "r"((a)[3]), "r"(b0), "r"(b1))

__device__ __forceinline__ float sgn(float v) {
    return (v > 0.0f) ? 1.0f : ((v < 0.0f) ? -1.0f : 0.0f);
}

__device__ __forceinline__ uint32_t h2u(__half2 h) {
    return *reinterpret_cast<uint32_t*>(&h);
}

// ---------------------------------------------------------------------------
// Prep: x -> fp16 (8 floats in, one 16B store out per thread)
// ---------------------------------------------------------------------------
__global__ void prep_x_kernel(const float4* __restrict__ x) {
    size_t i = (size_t)blockIdx.x * blockDim.x + threadIdx.x;
    float4 a = x[2 * i];
    float4 b = x[2 * i + 1];
    uint4 o;
    o.x = h2u(__floats2half2_rn(a.x, a.y));
    o.y = h2u(__floats2half2_rn(a.z, a.w));
    o.z = h2u(__floats2half2_rn(b.x, b.y));
    o.w = h2u(__floats2half2_rn(b.z, b.w));
    *reinterpret_cast<uint4*>(&g_xh[8 * i]) = o;
}

// Merged B1+B2 prep
__global__ void prep_B_kernel(const float* __restrict__ V,   const float* __restrict__ VR,
                              const float* __restrict__ v2,  const float* __restrict__ v2R,
                              const float* __restrict__ v1,  const float* __restrict__ v1R,
                              const float* __restrict__ u2,  const float* __restrict__ u2R,
                              const float* __restrict__ U,   const float* __restrict__ UR,
                              const float* __restrict__ u1,  const float* __restrict__ u1R) {
    int idx = blockIdx.x * blockDim.x + threadIdx.x;
    if (idx < S_CAT * DIN) {                       // B1[s][i]
        int s = idx >> 12;
        int i = idx & 4095;
        float val;
        if (s < S_RANK) val = sgn(V [(size_t)s * DIN + i]) * v2[i] * v1[s] * u2[s];
        else {
            int s2 = s - S_RANK;
            val = sgn(VR[(size_t)s2 * DIN + i]) * v2R[i] * v1R[s2] * u2R[s2];
        }
        g_B1[idx] = __float2half(val);
    } else {                                       // B2[j][s]
        int idx2 = idx - S_CAT * DIN;
        int j = idx2 >> 9;
        int s = idx2 & 511;
        float val;
        if (s < S_RANK) val = sgn(U [(size_t)j * S_RANK + s]) * u1[j];
        else            val = sgn(UR[(size_t)j * S_RANK + (s - S_RANK)]) * u1R[j];
        g_B2[idx2] = __float2half(val);
    }
}

// ---------------------------------------------------------------------------
// HMMA GEMM with fragment double-buffering.
// CTA 128x128, warps 2x4 of 64x32, 2 CTAs/SM, 3-stage cp.async.
// Per ks-block, LDSM for ks+1 issues BEFORE the MMAs of ks; ks=0 fragments
// preload right after the barrier (latency hidden behind cp.async issue).
// EPI==1: store fp16 to g_H.  EPI==2: add bias, streaming-store fp32 to out.
// ---------------------------------------------------------------------------
template <int K, int EPI>
__global__ __launch_bounds__(THREADS, 2) void gemm_kernel(float* __restrict__ out,
                                                          const float* __restrict__ bias) {
    extern __shared__ char smem_raw[];
    const uint32_t sm_tiles = smem_u32(smem_raw);
    const int tid  = threadIdx.x;
    const int wid  = tid >> 5;
    const int lane = tid & 31;
    const int m0 = blockIdx.y * BM;
    const int n0 = blockIdx.x * BN;
    constexpr int NIT = K / BK;
    constexpr int STAGE2 = 2 * TILE_BYTES;

    const __half* A = (EPI == 1) ? g_xh : g_H;
    const __half* B = (EPI == 1) ? g_B1 : g_B2;

    const int wm = wid >> 2;
    const int wn = wid & 3;

    const int ldRow = lane & 15;
    const int ldSel = lane >> 4;
    // Pre-swizzled per-i / per-jj base offsets. ks advances via XOR of ks*32
    // (valid: ks*32 touches bits 5-6 only; the SW128 XOR field derives from
    // bits 7-9, which ks doesn't change, and base bits 4-6 come from ldSel/
    // swizzle with no carries).
    uint32_t aPre[4], bPre[2];
    #pragma unroll
    for (int i = 0; i < 4; ++i)
        aPre[i] = SWZ((uint32_t)((wm * 64 + i * 16 + ldRow) * 128 + ldSel * 16));
    #pragma unroll
    for (int jj = 0; jj < 2; ++jj)
        bPre[jj] = SWZ((uint32_t)((wn * 32 + jj * 16 + ldRow) * 128 + ldSel * 16)) + TILE_BYTES;

    float acc[4][4][4] = {};   // 64 regs

    auto load_stage = [&](int it) {
        const uint32_t sbase = sm_tiles + (it % STAGES) * STAGE2;
        const int k0 = it * BK;
        #pragma unroll
        for (int u = 0; u < 8; ++u) {
            int q = tid + u * THREADS;
            if (q < 1024) {
                int row = q >> 3, c = q & 7;
                CP_ASYNC16(sbase + SWZ((uint32_t)(row * 128 + c * 16)),
                           A + (size_t)(m0 + row) * K + k0 + c * 8);
            } else {
                int qb = q - 1024;
                int row = qb >> 3, c = qb & 7;
                CP_ASYNC16(sbase + TILE_BYTES + SWZ((uint32_t)(row * 128 + c * 16)),
                           B + (size_t)(n0 + row) * K + k0 + c * 8);
            }
        }
    };

    // Prologue
    load_stage(0); CP_COMMIT();
    load_stage(1); CP_COMMIT();

    uint32_t af[2][4][4], bf[2][2][4];   // 48 regs

    #pragma unroll 1
    for (int it = 0; it < NIT; ++it) {
        CP_WAIT(1);
        __syncthreads();       // stage `it` resident; MMA(it-1) complete

        const uint32_t sbase = sm_tiles + (it % STAGES) * STAGE2;

        // Preload ks=0 fragments FIRST — their LDS latency hides behind the
        // cp.async issue burst below.
        #pragma unroll
        for (int i = 0; i < 4; ++i)
            LDMATRIX_X4(af[0][i][0], af[0][i][1], af[0][i][2], af[0][i][3],
                        sbase + aPre[i]);
        #pragma unroll
        for (int jj = 0; jj < 2; ++jj)
            LDMATRIX_X4(bf[0][jj][0], bf[0][jj][1], bf[0][jj][2], bf[0][jj][3],
                        sbase + bPre[jj]);

        if (it + 2 < NIT) load_stage(it + 2);
        CP_COMMIT();

        #pragma unroll
        for (int ks = 0; ks < 4; ++ks) {
            const int cur = ks & 1, nxt = cur ^ 1;
            if (ks < 3) {
                const uint32_t kx = (uint32_t)((ks + 1) * 32);
                #pragma unroll
                for (int i = 0; i < 4; ++i)
                    LDMATRIX_X4(af[nxt][i][0], af[nxt][i][1], af[nxt][i][2], af[nxt][i][3],
                                sbase + (aPre[i] ^ kx));
                #pragma unroll
                for (int jj = 0; jj < 2; ++jj)
                    LDMATRIX_X4(bf[nxt][jj][0], bf[nxt][jj][1], bf[nxt][jj][2], bf[nxt][jj][3],
                                sbase + (bPre[jj] ^ kx));
            }
            #pragma unroll
            for (int i = 0; i < 4; ++i)
                #pragma unroll
                for (int j = 0; j < 4; ++j)
                    MMA_16816(acc[i][j], af[cur][i],
                              bf[cur][j >> 1][(j & 1)], bf[cur][j >> 1][(j & 1) + 2]);
        }
        __syncthreads();       // all warps done reading stage `it`
    }

    // Epilogue
    const int rBase = m0 + wm * 64 + (lane >> 2);
    const int cBase = n0 + wn * 32 + (lane & 3) * 2;
    #pragma unroll
    for (int i = 0; i < 4; ++i) {
        const int r = rBase + i * 16;
        #pragma unroll
        for (int j = 0; j < 4; ++j) {
            const int c = cBase + j * 8;
            if (EPI == 1) {
                *(__half2*)&g_H[(size_t)r * S_CAT + c] =
                    __floats2half2_rn(acc[i][j][0], acc[i][j][1]);
                *(__half2*)&g_H[(size_t)(r + 8) * S_CAT + c] =
                    __floats2half2_rn(acc[i][j][2], acc[i][j][3]);
            } else {
                const float b0 = bias[c], b1 = bias[c + 1];
                float2 v0 = make_float2(acc[i][j][0] + b0, acc[i][j][1] + b1);
                float2 v1 = make_float2(acc[i][j][2] + b0, acc[i][j][3] + b1);
                __stcs((float2*)&out[(size_t)r * DOUT + c], v0);          // streaming:
                __stcs((float2*)&out[(size_t)(r + 8) * DOUT + c], v1);    // write-once data
            }
        }
    }
}

// ---------------------------------------------------------------------------
// Launch
// ---------------------------------------------------------------------------
extern "C" void kernel_launch(void* const* d_in, const int* in_sizes, int n_in,
                              void* d_out, int out_size) {
    const float* x    = (const float*)d_in[0];
    const float* V    = (const float*)d_in[1];
    const float* U    = (const float*)d_in[2];
    const float* v1   = (const float*)d_in[3];
    const float* v2   = (const float*)d_in[4];
    const float* u1   = (const float*)d_in[5];
    const float* u2   = (const float*)d_in[6];
    const float* V_R  = (const float*)d_in[7];
    const float* U_R  = (const float*)d_in[8];
    const float* v1_R = (const float*)d_in[9];
    const float* v2_R = (const float*)d_in[10];
    const float* u1_R = (const float*)d_in[11];
    const float* u2_R = (const float*)d_in[12];
    const float* bias = (const float*)d_in[13];
    float* out = (float*)d_out;

    cudaFuncSetAttribute(gemm_kernel<DIN, 1>,
                         cudaFuncAttributeMaxDynamicSharedMemorySize, G_SMEM);
    cudaFuncSetAttribute(gemm_kernel<S_CAT, 2>,
                         cudaFuncAttributeMaxDynamicSharedMemorySize, G_SMEM);

    prep_x_kernel<<<(int)((size_t)N_TOK * DIN / 8 / 256), 256>>>((const float4*)x);
    prep_B_kernel<<<(S_CAT * DIN + DOUT * S_CAT) / 256, 256>>>(
        V, V_R, v2, v2_R, v1, v1_R, u2, u2_R, U, U_R, u1, u1_R);

    // GEMM1: H = fp16(x) @ B1^T   grid (4, 64) = 256 CTAs, 2/SM
    gemm_kernel<DIN, 1><<<dim3(S_CAT / BN, N_TOK / BM), THREADS, G_SMEM>>>(nullptr, nullptr);

    // GEMM2: y = H @ B2^T + bias  grid (32, 64) = 2048 CTAs, 2/SM
    gemm_kernel<S_CAT, 2><<<dim3(DOUT / BN, N_TOK / BM), THREADS, G_SMEM>>>(out, bias);
}

// round 14
// speedup vs baseline: 1.0207x; 1.0207x over previous
#include <cuda_runtime.h>
#include <cuda_fp16.h>
#include <cstdint>
#include <cstddef>

// ---------------------------------------------------------------------------
// Problem constants
// ---------------------------------------------------------------------------
#define N_TOK   8192
#define DIN     4096
#define DOUT    4096
#define S_RANK  256
#define S_CAT   512

#define BM      128
#define BN      128
#define BK      64          // 64 fp16 = 128B row -> SW128 swizzle
#define STAGES  3
#define THREADS 256

#define TILE_BYTES (128 * 128)                       // 16KB per fp16 tile stage
#define G_SMEM     (STAGES * 2 * TILE_BYTES)         // 98304 -> 2 CTAs/SM

// Merged prep grid split
#define NX_BLOCKS  16384     // (N_TOK*DIN/8)/256  : x conversion part
#define NB_BLOCKS  16384     // (S_CAT*DIN + DOUT*S_CAT)/256 : B prep part

// ---------------------------------------------------------------------------
// Scratch (device globals; no runtime allocation)
// ---------------------------------------------------------------------------
__device__ __half g_xh[(size_t)N_TOK * DIN];     // fp16(x)            64 MB
__device__ __half g_B1[(size_t)S_CAT * DIN];     // sign(V)*v2*v1*u2    4 MB
__device__ __half g_B2[(size_t)DOUT * S_CAT];    // sign(U)*u1          4 MB
__device__ __half g_H [(size_t)N_TOK * S_CAT];   // H fp16              8 MB

// ---------------------------------------------------------------------------
// Helpers
// ---------------------------------------------------------------------------
__device__ __forceinline__ uint32_t smem_u32(const void* p) {
    uint32_t a;
    asm("{ .reg .u64 t; cvta.to.shared.u64 t, %1; cvt.u32.u64 %0, t; }" : "=r"(a) : "l"(p));
    return a;
}

#define SWZ(o) ((o) ^ (((o) >> 3) & 0x70))

#define CP_ASYNC16(s, g) \
    asm volatile("cp.async.cg.shared.global [%0], [%1], 16;" :: "r"(s), "l"(g))
#define CP_COMMIT() asm volatile("cp.async.commit_group;")
#define CP_WAIT(n)  asm volatile("cp.async.wait_group %0;" :: "n"(n) : "memory")

#define LDMATRIX_X4(r0, r1, r2, r3, addr)                                     \
    asm volatile("ldmatrix.sync.aligned.m8n8.x4.shared.b16 {%0,%1,%2,%3}, [%4];" \
        : "=r"(r0), "=r"(r1), "=r"(r2), "=r"(r3) : "r"(addr))

#define MMA_16816(d, a, b0, b1)                                               \
    asm volatile("mma.sync.aligned.m16n8k16.row.col.f32.f16.f16.f32 "         \
        "{%0,%1,%2,%3}, {%4,%5,%6,%7}, {%8,%9}, {%0,%1,%2,%3};"               \
        : "+f"((d)[0]), "+f"((d)[1]), "+f"((d)[2]), "+f"((d)[3])              \
        : "r"((a)[0]), "r"((a)[1]), "r"((a)[2]), "r"((a)[3]), "r"(b0), "r"(b1))

__device__ __forceinline__ float sgn(float v) {
    return (v > 0.0f) ? 1.0f : ((v < 0.0f) ? -1.0f : 0.0f);
}

__device__ __forceinline__ uint32_t h2u(__half2 h) {
    return *reinterpret_cast<uint32_t*>(&h);
}

// ---------------------------------------------------------------------------
// Merged prep: blocks [0, NX_BLOCKS) convert x -> fp16 (8 floats/thread);
// blocks [NX_BLOCKS, NX_BLOCKS+NB_BLOCKS) build B1/B2. B prep rides inside
// the DRAM-bound shadow of the x conversion.
// ---------------------------------------------------------------------------
__global__ void prep_all_kernel(const float4* __restrict__ x,
                                const float* __restrict__ V,   const float* __restrict__ VR,
                                const float* __restrict__ v2,  const float* __restrict__ v2R,
                                const float* __restrict__ v1,  const float* __restrict__ v1R,
                                const float* __restrict__ u2,  const float* __restrict__ u2R,
                                const float* __restrict__ U,   const float* __restrict__ UR,
                                const float* __restrict__ u1,  const float* __restrict__ u1R) {
    const int b = blockIdx.x;
    if (b < NX_BLOCKS) {
        size_t i = (size_t)b * blockDim.x + threadIdx.x;
        float4 a = x[2 * i];
        float4 c = x[2 * i + 1];
        uint4 o;
        o.x = h2u(__floats2half2_rn(a.x, a.y));
        o.y = h2u(__floats2half2_rn(a.z, a.w));
        o.z = h2u(__floats2half2_rn(c.x, c.y));
        o.w = h2u(__floats2half2_rn(c.z, c.w));
        *reinterpret_cast<uint4*>(&g_xh[8 * i]) = o;
    } else {
        int idx = (b - NX_BLOCKS) * blockDim.x + threadIdx.x;
        if (idx < S_CAT * DIN) {                   // B1[s][i]
            int s = idx >> 12;
            int i = idx & 4095;
            float val;
            if (s < S_RANK) val = sgn(V [(size_t)s * DIN + i]) * v2[i] * v1[s] * u2[s];
            else {
                int s2 = s - S_RANK;
                val = sgn(VR[(size_t)s2 * DIN + i]) * v2R[i] * v1R[s2] * u2R[s2];
            }
            g_B1[idx] = __float2half(val);
        } else {                                   // B2[j][s]
            int idx2 = idx - S_CAT * DIN;
            int j = idx2 >> 9;
            int s = idx2 & 511;
            float val;
            if (s < S_RANK) val = sgn(U [(size_t)j * S_RANK + s]) * u1[j];
            else            val = sgn(UR[(size_t)j * S_RANK + (s - S_RANK)]) * u1R[j];
            g_B2[idx2] = __float2half(val);
        }
    }
}

// ---------------------------------------------------------------------------
// HMMA GEMM (R11 champion structure): C[M,N] = A[M,K] @ B[N,K]^T.
// CTA 128x128, warps 2x4 of 64x32, 2 CTAs/SM, 3-stage cp.async, prefetch
// before MMA. Single-buffer fragments (R11); precomputed swizzled offsets
// with XOR ks-stepping (alu reduction only — no extra register pressure).
// EPI==1: store fp16 to g_H.  EPI==2: add bias, store fp32 to out.
// ---------------------------------------------------------------------------
template <int K, int EPI>
__global__ __launch_bounds__(THREADS, 2) void gemm_kernel(float* __restrict__ out,
                                                          const float* __restrict__ bias) {
    extern __shared__ char smem_raw[];
    const uint32_t sm_tiles = smem_u32(smem_raw);
    const int tid  = threadIdx.x;
    const int wid  = tid >> 5;
    const int lane = tid & 31;
    const int m0 = blockIdx.y * BM;
    const int n0 = blockIdx.x * BN;
    constexpr int NIT = K / BK;
    constexpr int STAGE2 = 2 * TILE_BYTES;

    const __half* A = (EPI == 1) ? g_xh : g_H;
    const __half* B = (EPI == 1) ? g_B1 : g_B2;

    const int wm = wid >> 2;
    const int wn = wid & 3;

    const int ldRow = lane & 15;
    const int ldSel = lane >> 4;
    // Pre-swizzled fragment base offsets; ks stepping via XOR of ks*32.
    // Valid because pre-swizzle base bits 5-6 are zero (row*128 | ldSel*16),
    // so SWZ(base + ks*32) == SWZ(base) ^ (ks*32).
    uint32_t aPre[4], bPre[2];
    #pragma unroll
    for (int i = 0; i < 4; ++i)
        aPre[i] = SWZ((uint32_t)((wm * 64 + i * 16 + ldRow) * 128 + ldSel * 16));
    #pragma unroll
    for (int jj = 0; jj < 2; ++jj)
        bPre[jj] = SWZ((uint32_t)((wn * 32 + jj * 16 + ldRow) * 128 + ldSel * 16)) + TILE_BYTES;

    float acc[4][4][4] = {};   // 64 regs

    auto load_stage = [&](int it) {
        const uint32_t sbase = sm_tiles + (it % STAGES) * STAGE2;
        const int k0 = it * BK;
        #pragma unroll
        for (int u = 0; u < 8; ++u) {
            int q = tid + u * THREADS;
            if (q < 1024) {
                int row = q >> 3, c = q & 7;
                CP_ASYNC16(sbase + SWZ((uint32_t)(row * 128 + c * 16)),
                           A + (size_t)(m0 + row) * K + k0 + c * 8);
            } else {
                int qb = q - 1024;
                int row = qb >> 3, c = qb & 7;
                CP_ASYNC16(sbase + TILE_BYTES + SWZ((uint32_t)(row * 128 + c * 16)),
                           B + (size_t)(n0 + row) * K + k0 + c * 8);
            }
        }
    };

    // Prologue
    load_stage(0); CP_COMMIT();
    load_stage(1); CP_COMMIT();

    #pragma unroll 1
    for (int it = 0; it < NIT; ++it) {
        CP_WAIT(1);
        __syncthreads();       // stage `it` resident; MMA(it-1) complete

        if (it + 2 < NIT) load_stage(it + 2);
        CP_COMMIT();

        const uint32_t sbase = sm_tiles + (it % STAGES) * STAGE2;

        #pragma unroll
        for (int ks = 0; ks < 4; ++ks) {
            const uint32_t kx = (uint32_t)(ks * 32);
            uint32_t af[4][4], bf[2][4];
            #pragma unroll
            for (int i = 0; i < 4; ++i)
                LDMATRIX_X4(af[i][0], af[i][1], af[i][2], af[i][3],
                            sbase + (aPre[i] ^ kx));
            #pragma unroll
            for (int jj = 0; jj < 2; ++jj)
                LDMATRIX_X4(bf[jj][0], bf[jj][1], bf[jj][2], bf[jj][3],
                            sbase + (bPre[jj] ^ kx));
            #pragma unroll
            for (int i = 0; i < 4; ++i)
                #pragma unroll
                for (int j = 0; j < 4; ++j)
                    MMA_16816(acc[i][j], af[i], bf[j >> 1][(j & 1)], bf[j >> 1][(j & 1) + 2]);
        }
        __syncthreads();       // all warps done reading stage `it`
    }

    // Epilogue
    const int rBase = m0 + wm * 64 + (lane >> 2);
    const int cBase = n0 + wn * 32 + (lane & 3) * 2;
    #pragma unroll
    for (int i = 0; i < 4; ++i) {
        const int r = rBase + i * 16;
        #pragma unroll
        for (int j = 0; j < 4; ++j) {
            const int c = cBase + j * 8;
            if (EPI == 1) {
                *(__half2*)&g_H[(size_t)r * S_CAT + c] =
                    __floats2half2_rn(acc[i][j][0], acc[i][j][1]);
                *(__half2*)&g_H[(size_t)(r + 8) * S_CAT + c] =
                    __floats2half2_rn(acc[i][j][2], acc[i][j][3]);
            } else {
                const float b0 = bias[c], b1 = bias[c + 1];
                float2 v0 = make_float2(acc[i][j][0] + b0, acc[i][j][1] + b1);
                float2 v1 = make_float2(acc[i][j][2] + b0, acc[i][j][3] + b1);
                *(float2*)&out[(size_t)r * DOUT + c] = v0;
                *(float2*)&out[(size_t)(r + 8) * DOUT + c] = v1;
            }
        }
    }
}

// ---------------------------------------------------------------------------
// Launch
// ---------------------------------------------------------------------------
extern "C" void kernel_launch(void* const* d_in, const int* in_sizes, int n_in,
                              void* d_out, int out_size) {
    const float* x    = (const float*)d_in[0];
    const float* V    = (const float*)d_in[1];
    const float* U    = (const float*)d_in[2];
    const float* v1   = (const float*)d_in[3];
    const float* v2   = (const float*)d_in[4];
    const float* u1   = (const float*)d_in[5];
    const float* u2   = (const float*)d_in[6];
    const float* V_R  = (const float*)d_in[7];
    const float* U_R  = (const float*)d_in[8];
    const float* v1_R = (const float*)d_in[9];
    const float* v2_R = (const float*)d_in[10];
    const float* u1_R = (const float*)d_in[11];
    const float* u2_R = (const float*)d_in[12];
    const float* bias = (const float*)d_in[13];
    float* out = (float*)d_out;

    cudaFuncSetAttribute(gemm_kernel<DIN, 1>,
                         cudaFuncAttributeMaxDynamicSharedMemorySize, G_SMEM);
    cudaFuncSetAttribute(gemm_kernel<S_CAT, 2>,
                         cudaFuncAttributeMaxDynamicSharedMemorySize, G_SMEM);

    // Single merged prep launch
    prep_all_kernel<<<NX_BLOCKS + NB_BLOCKS, 256>>>(
        (const float4*)x, V, V_R, v2, v2_R, v1, v1_R, u2, u2_R, U, U_R, u1, u1_R);

    // GEMM1: H = fp16(x) @ B1^T   grid (4, 64) = 256 CTAs, 2/SM
    gemm_kernel<DIN, 1><<<dim3(S_CAT / BN, N_TOK / BM), THREADS, G_SMEM>>>(nullptr, nullptr);

    // GEMM2: y = H @ B2^T + bias  grid (32, 64) = 2048 CTAs, 2/SM
    gemm_kernel<S_CAT, 2><<<dim3(DOUT / BN, N_TOK / BM), THREADS, G_SMEM>>>(out, bias);
}

// round 15
// speedup vs baseline: 1.0950x; 1.0728x over previous
#include <cuda_runtime.h>
#include <cuda_fp16.h>
#include <cstdint>
#include <cstddef>

// ---------------------------------------------------------------------------
// Problem constants
// ---------------------------------------------------------------------------
#define N_TOK   8192
#define DIN     4096
#define DOUT    4096
#define S_RANK  256
#define S_CAT   512

#define BM      128
#define BN      128
#define BK      64          // 64 fp16 = 128B row -> SW128 swizzle
#define STAGES  3
#define THREADS 256

#define TILE_BYTES (128 * 128)                       // 16KB per fp16 tile stage
#define G_SMEM     (STAGES * 2 * TILE_BYTES)         // 98304 -> 2 CTAs/SM

// ---------------------------------------------------------------------------
// Scratch (device globals; no runtime allocation)
// ---------------------------------------------------------------------------
__device__ __half g_xh[(size_t)N_TOK * DIN];     // fp16(x)            64 MB
__device__ __half g_B1[(size_t)S_CAT * DIN];     // sign(V)*v2*v1*u2    4 MB
__device__ __half g_B2[(size_t)DOUT * S_CAT];    // sign(U)*u1          4 MB
__device__ __half g_H [(size_t)N_TOK * S_CAT];   // H fp16              8 MB

// ---------------------------------------------------------------------------
// Helpers
// ---------------------------------------------------------------------------
__device__ __forceinline__ uint32_t smem_u32(const void* p) {
    uint32_t a;
    asm("{ .reg .u64 t; cvta.to.shared.u64 t, %1; cvt.u32.u64 %0, t; }" : "=r"(a) : "l"(p));
    return a;
}

#define SWZ(o) ((o) ^ (((o) >> 3) & 0x70))

#define CP_ASYNC16(s, g) \
    asm volatile("cp.async.cg.shared.global [%0], [%1], 16;" :: "r"(s), "l"(g))
#define CP_COMMIT() asm volatile("cp.async.commit_group;")
#define CP_WAIT(n)  asm volatile("cp.async.wait_group %0;" :: "n"(n) : "memory")

#define LDMATRIX_X4(r0, r1, r2, r3, addr)                                     \
    asm volatile("ldmatrix.sync.aligned.m8n8.x4.shared.b16 {%0,%1,%2,%3}, [%4];" \
        : "=r"(r0), "=r"(r1), "=r"(r2), "=r"(r3) : "r"(addr))

#define MMA_16816(d, a, b0, b1)                                               \
    asm volatile("mma.sync.aligned.m16n8k16.row.col.f32.f16.f16.f32 "         \
        "{%0,%1,%2,%3}, {%4,%5,%6,%7}, {%8,%9}, {%0,%1,%2,%3};"               \
        : "+f"((d)[0]), "+f"((d)[1]), "+f"((d)[2]), "+f"((d)[3])              \
        : "r"((a)[0]), "r"((a)[1]), "r"((a)[2]), "r"((a)[3]), "r"(b0), "r"(b1))

__device__ __forceinline__ float sgn(float v) {
    return (v > 0.0f) ? 1.0f : ((v < 0.0f) ? -1.0f : 0.0f);
}

__device__ __forceinline__ uint32_t h2u(__half2 h) {
    return *reinterpret_cast<uint32_t*>(&h);
}

// ---------------------------------------------------------------------------
// Prep: x -> fp16. 16 floats/thread (4x LDG.128, 2x STG.128) for MLP.
// ---------------------------------------------------------------------------
__global__ void prep_x_kernel(const float4* __restrict__ x) {
    size_t i = (size_t)blockIdx.x * blockDim.x + threadIdx.x;
    float4 a = x[4 * i];
    float4 b = x[4 * i + 1];
    float4 c = x[4 * i + 2];
    float4 d = x[4 * i + 3];
    uint4 o0, o1;
    o0.x = h2u(__floats2half2_rn(a.x, a.y));
    o0.y = h2u(__floats2half2_rn(a.z, a.w));
    o0.z = h2u(__floats2half2_rn(b.x, b.y));
    o0.w = h2u(__floats2half2_rn(b.z, b.w));
    o1.x = h2u(__floats2half2_rn(c.x, c.y));
    o1.y = h2u(__floats2half2_rn(c.z, c.w));
    o1.z = h2u(__floats2half2_rn(d.x, d.y));
    o1.w = h2u(__floats2half2_rn(d.z, d.w));
    uint4* dst = reinterpret_cast<uint4*>(&g_xh[16 * i]);
    dst[0] = o0;
    dst[1] = o1;
}

// Vectorized B prep: 8 elements/thread, uint4 stores.
// Threads [0, S_CAT*DIN/8): B1. Threads [S_CAT*DIN/8, +DOUT*S_CAT/8): B2.
__global__ void prep_B_kernel(const float* __restrict__ V,   const float* __restrict__ VR,
                              const float* __restrict__ v2,  const float* __restrict__ v2R,
                              const float* __restrict__ v1,  const float* __restrict__ v1R,
                              const float* __restrict__ u2,  const float* __restrict__ u2R,
                              const float* __restrict__ U,   const float* __restrict__ UR,
                              const float* __restrict__ u1,  const float* __restrict__ u1R) {
    int t = blockIdx.x * blockDim.x + threadIdx.x;
    constexpr int NB1 = S_CAT * DIN / 8;           // 262144
    float src[8], scl[8];
    __half hv[8];
    if (t < NB1) {                                 // B1[s][i0..i0+7]
        int e0 = t * 8;
        int s  = e0 >> 12;
        int i0 = e0 & 4095;
        float rs;                                  // row scale v1*u2
        const float* vrow;
        const float* v2p;
        if (s < S_RANK) { vrow = V  + (size_t)s * DIN;            v2p = v2;  rs = v1[s] * u2[s]; }
        else { int s2 = s - S_RANK; vrow = VR + (size_t)s2 * DIN; v2p = v2R; rs = v1R[s2] * u2R[s2]; }
        *(float4*)&src[0] = *(const float4*)&vrow[i0];
        *(float4*)&src[4] = *(const float4*)&vrow[i0 + 4];
        *(float4*)&scl[0] = *(const float4*)&v2p[i0];
        *(float4*)&scl[4] = *(const float4*)&v2p[i0 + 4];
        #pragma unroll
        for (int k = 0; k < 8; ++k) hv[k] = __float2half(sgn(src[k]) * scl[k] * rs);
        *(uint4*)&g_B1[e0] = *(uint4*)&hv[0];
    } else {                                       // B2[j][s0..s0+7]
        int e0 = (t - NB1) * 8;
        int j  = e0 >> 9;
        int s0 = e0 & 511;
        float cs;
        const float* urow;
        if (s0 < S_RANK) { urow = U  + (size_t)j * S_RANK + s0;            cs = u1[j]; }
        else {             urow = UR + (size_t)j * S_RANK + (s0 - S_RANK); cs = u1R[j]; }
        *(float4*)&src[0] = *(const float4*)&urow[0];
        *(float4*)&src[4] = *(const float4*)&urow[4];
        #pragma unroll
        for (int k = 0; k < 8; ++k) hv[k] = __float2half(sgn(src[k]) * cs);
        *(uint4*)&g_B2[e0] = *(uint4*)&hv[0];
    }
}

// ---------------------------------------------------------------------------
// HMMA GEMM — EXACT R11 champion body: C[M,N] = A[M,K] @ B[N,K]^T.
// CTA 128x128, warps 2x4 of 64x32, 2 CTAs/SM, 3-stage cp.async, prefetch
// before MMA, single-buffer fragments, recomputed swizzle addressing.
// EPI==1: store fp16 to g_H.  EPI==2: add bias, store fp32 to out.
// ---------------------------------------------------------------------------
template <int K, int EPI>
__global__ __launch_bounds__(THREADS, 2) void gemm_kernel(float* __restrict__ out,
                                                          const float* __restrict__ bias) {
    extern __shared__ char smem_raw[];
    const uint32_t sm_tiles = smem_u32(smem_raw);
    const int tid  = threadIdx.x;
    const int wid  = tid >> 5;
    const int lane = tid & 31;
    const int m0 = blockIdx.y * BM;
    const int n0 = blockIdx.x * BN;
    constexpr int NIT = K / BK;
    constexpr int STAGE2 = 2 * TILE_BYTES;

    const __half* A = (EPI == 1) ? g_xh : g_H;
    const __half* B = (EPI == 1) ? g_B1 : g_B2;

    const int wm = wid >> 2;
    const int wn = wid & 3;

    const int ldRow = lane & 15;
    const int ldSel = lane >> 4;
    const uint32_t aOffBase = (uint32_t)((wm * 64 + ldRow) * 128 + ldSel * 16);
    const uint32_t bOffBase = (uint32_t)((wn * 32 + ldRow) * 128 + ldSel * 16);

    float acc[4][4][4] = {};   // 64 regs

    auto load_stage = [&](int it) {
        const uint32_t sbase = sm_tiles + (it % STAGES) * STAGE2;
        const int k0 = it * BK;
        #pragma unroll
        for (int u = 0; u < 8; ++u) {
            int q = tid + u * THREADS;
            if (q < 1024) {
                int row = q >> 3, c = q & 7;
                CP_ASYNC16(sbase + SWZ((uint32_t)(row * 128 + c * 16)),
                           A + (size_t)(m0 + row) * K + k0 + c * 8);
            } else {
                int qb = q - 1024;
                int row = qb >> 3, c = qb & 7;
                CP_ASYNC16(sbase + TILE_BYTES + SWZ((uint32_t)(row * 128 + c * 16)),
                           B + (size_t)(n0 + row) * K + k0 + c * 8);
            }
        }
    };

    // Prologue
    load_stage(0); CP_COMMIT();
    load_stage(1); CP_COMMIT();

    #pragma unroll 1
    for (int it = 0; it < NIT; ++it) {
        CP_WAIT(1);
        __syncthreads();       // stage `it` resident; MMA(it-1) complete

        if (it + 2 < NIT) load_stage(it + 2);
        CP_COMMIT();

        const uint32_t sA = sm_tiles + (it % STAGES) * STAGE2;
        const uint32_t sB = sA + TILE_BYTES;

        #pragma unroll
        for (int ks = 0; ks < 4; ++ks) {
            uint32_t af[4][4], bf[2][4];
            #pragma unroll
            for (int i = 0; i < 4; ++i)
                LDMATRIX_X4(af[i][0], af[i][1], af[i][2], af[i][3],
                            sA + SWZ(aOffBase + (uint32_t)(i * 2048 + ks * 32)));
            #pragma unroll
            for (int jj = 0; jj < 2; ++jj)
                LDMATRIX_X4(bf[jj][0], bf[jj][1], bf[jj][2], bf[jj][3],
                            sB + SWZ(bOffBase + (uint32_t)(jj * 2048 + ks * 32)));
            #pragma unroll
            for (int i = 0; i < 4; ++i)
                #pragma unroll
                for (int j = 0; j < 4; ++j)
                    MMA_16816(acc[i][j], af[i], bf[j >> 1][(j & 1)], bf[j >> 1][(j & 1) + 2]);
        }
        __syncthreads();       // all warps done reading stage `it`
    }

    // Epilogue
    const int rBase = m0 + wm * 64 + (lane >> 2);
    const int cBase = n0 + wn * 32 + (lane & 3) * 2;
    #pragma unroll
    for (int i = 0; i < 4; ++i) {
        const int r = rBase + i * 16;
        #pragma unroll
        for (int j = 0; j < 4; ++j) {
            const int c = cBase + j * 8;
            if (EPI == 1) {
                *(__half2*)&g_H[(size_t)r * S_CAT + c] =
                    __floats2half2_rn(acc[i][j][0], acc[i][j][1]);
                *(__half2*)&g_H[(size_t)(r + 8) * S_CAT + c] =
                    __floats2half2_rn(acc[i][j][2], acc[i][j][3]);
            } else {
                const float b0 = bias[c], b1 = bias[c + 1];
                float2 v0 = make_float2(acc[i][j][0] + b0, acc[i][j][1] + b1);
                float2 v1 = make_float2(acc[i][j][2] + b0, acc[i][j][3] + b1);
                *(float2*)&out[(size_t)r * DOUT + c] = v0;
                *(float2*)&out[(size_t)(r + 8) * DOUT + c] = v1;
            }
        }
    }
}

// ---------------------------------------------------------------------------
// Launch
// ---------------------------------------------------------------------------
extern "C" void kernel_launch(void* const* d_in, const int* in_sizes, int n_in,
                              void* d_out, int out_size) {
    const float* x    = (const float*)d_in[0];
    const float* V    = (const float*)d_in[1];
    const float* U    = (const float*)d_in[2];
    const float* v1   = (const float*)d_in[3];
    const float* v2   = (const float*)d_in[4];
    const float* u1   = (const float*)d_in[5];
    const float* u2   = (const float*)d_in[6];
    const float* V_R  = (const float*)d_in[7];
    const float* U_R  = (const float*)d_in[8];
    const float* v1_R = (const float*)d_in[9];
    const float* v2_R = (const float*)d_in[10];
    const float* u1_R = (const float*)d_in[11];
    const float* u2_R = (const float*)d_in[12];
    const float* bias = (const float*)d_in[13];
    float* out = (float*)d_out;

    cudaFuncSetAttribute(gemm_kernel<DIN, 1>,
                         cudaFuncAttributeMaxDynamicSharedMemorySize, G_SMEM);
    cudaFuncSetAttribute(gemm_kernel<S_CAT, 2>,
                         cudaFuncAttributeMaxDynamicSharedMemorySize, G_SMEM);

    // Prep: x conversion (16 floats/thread) + vectorized B prep
    prep_x_kernel<<<(int)((size_t)N_TOK * DIN / 16 / 256), 256>>>((const float4*)x);
    prep_B_kernel<<<(S_CAT * DIN + DOUT * S_CAT) / 8 / 256, 256>>>(
        V, V_R, v2, v2_R, v1, v1_R, u2, u2_R, U, U_R, u1, u1_R);

    // GEMM1: H = fp16(x) @ B1^T   grid (4, 64) = 256 CTAs, 2/SM
    gemm_kernel<DIN, 1><<<dim3(S_CAT / BN, N_TOK / BM), THREADS, G_SMEM>>>(nullptr, nullptr);

    // GEMM2: y = H @ B2^T + bias  grid (32, 64) = 2048 CTAs, 2/SM
    gemm_kernel<S_CAT, 2><<<dim3(DOUT / BN, N_TOK / BM), THREADS, G_SMEM>>>(out, bias);
}